// round 6
// baseline (speedup 1.0000x reference)
#include <cuda_runtime.h>
#include <math.h>
#include <stdint.h>

// Problem constants
#define NN 64
#define TT 128
#define DD 512
#define HH 1024
#define G4 4096   // 4*H

// ---------------- scratch (device globals; no allocations) ----------------
__device__ __align__(16) float  g_Xa[(NN * TT) * G4];   // 128 MB: x@Wx + b
__device__ __align__(16) float  g_P[(NN * 16) * G4];    // 16 MB: packed [n][l][c][gate]
__device__ __align__(16) float  g_WhT[HH * G4];         // 16 MB: packed [k][c][gate]
__device__ __align__(16) float  g_A2[(NN * 16) * HH];   // 4 MB
__device__ __align__(16) float2 g_hT[2][HH * NN];       // h dup (h,h), layout [parity][c][n]
__device__ float g_scores[3][NN * 16];
__device__ volatile unsigned g_bar;

// ---------------- helpers ----------------
__device__ __forceinline__ unsigned long long fma2(unsigned long long a,
                                                   unsigned long long b,
                                                   unsigned long long c) {
    unsigned long long d;
    asm("fma.rn.f32x2 %0, %1, %2, %3;" : "=l"(d) : "l"(a), "l"(b), "l"(c));
    return d;
}
__device__ __forceinline__ unsigned long long dup2(float v) {
    unsigned long long r;
    asm("mov.b64 %0, {%1, %1};" : "=l"(r) : "f"(v));
    return r;
}
__device__ __forceinline__ unsigned long long pack2(float lo, float hi) {
    unsigned long long r;
    asm("mov.b64 %0, {%1, %2};" : "=l"(r) : "f"(lo), "f"(hi));
    return r;
}
__device__ __forceinline__ float2 unpack2(unsigned long long v) {
    float2 f;
    asm("mov.b64 {%0, %1}, %2;" : "=f"(f.x), "=f"(f.y) : "l"(v));
    return f;
}
__device__ __forceinline__ uint32_t smem_u32(const void* p) {
    return (uint32_t)__cvta_generic_to_shared(p);
}
__device__ __forceinline__ void cp_async16(uint32_t dst, const void* src) {
    asm volatile("cp.async.cg.shared.global [%0], [%1], 16;" :: "r"(dst), "l"(src) : "memory");
}

// ---------------- weight packing ----------------
__global__ void __launch_bounds__(256) pack_wh_kernel(const float* __restrict__ Wh) {
    int idx = blockIdx.x * 256 + threadIdx.x;
    int k = idx >> 10;
    int c = idx & 1023;
    const float* row = Wh + k * G4;
    float4 v;
    v.x = row[c];
    v.y = row[1024 + c];
    v.z = row[2048 + c];
    v.w = row[3072 + c];
    *(float4*)&g_WhT[idx * 4] = v;
}

__global__ void __launch_bounds__(256) transposeA_kernel(const float* __restrict__ A) {
    int idx = blockIdx.x * 256 + threadIdx.x;
    int r = idx >> 10;
    int k = idx & 1023;
    int n = r >> 4;
    int l = r & 15;
    g_A2[idx] = A[((n << 10) + k) * 16 + l];
}

// ---------------- tiled SGEMM (unchanged from R2) ----------------
template <int MODE>
__global__ void __launch_bounds__(256) sgemm_kernel(const float* __restrict__ Ain,
                                                    const float* __restrict__ B,
                                                    const float* __restrict__ bias,
                                                    int M, int N, int K) {
    __shared__ float As[16][128];
    __shared__ float Bs[16][64];

    const float* Amat = (MODE == 1) ? (const float*)g_A2 : Ain;
    float* C = (MODE == 1) ? (float*)g_P : (float*)g_Xa;

    const int tid = threadIdx.x;
    const int trow = tid >> 4;
    const int tcol = tid & 15;
    const int m0 = blockIdx.y * 128;
    const int n0 = blockIdx.x * 64;

    unsigned long long acc01[8], acc23[8];
#pragma unroll
    for (int i = 0; i < 8; i++) { acc01[i] = 0ULL; acc23[i] = 0ULL; }

    for (int k0 = 0; k0 < K; k0 += 16) {
#pragma unroll
        for (int p = 0; p < 2; p++) {
            int i = tid + p * 256;
            int m = i >> 2;
            int kq = (i & 3) * 4;
            float4 v = *(const float4*)&Amat[(long)(m0 + m) * K + k0 + kq];
            As[kq + 0][m] = v.x;
            As[kq + 1][m] = v.y;
            As[kq + 2][m] = v.z;
            As[kq + 3][m] = v.w;
        }
        {
            int k = tid >> 4;
            int nq = (tid & 15) * 4;
            *(float4*)&Bs[k][nq] = *(const float4*)&B[(long)(k0 + k) * N + n0 + nq];
        }
        __syncthreads();

#pragma unroll
        for (int kk = 0; kk < 16; kk++) {
            float a0[8];
            float4 av0 = *(float4*)&As[kk][trow * 8];
            float4 av1 = *(float4*)&As[kk][trow * 8 + 4];
            a0[0] = av0.x; a0[1] = av0.y; a0[2] = av0.z; a0[3] = av0.w;
            a0[4] = av1.x; a0[5] = av1.y; a0[6] = av1.z; a0[7] = av1.w;
            ulonglong2 bv = *(ulonglong2*)&Bs[kk][tcol * 4];
#pragma unroll
            for (int i = 0; i < 8; i++) {
                unsigned long long ad = dup2(a0[i]);
                acc01[i] = fma2(ad, bv.x, acc01[i]);
                acc23[i] = fma2(ad, bv.y, acc23[i]);
            }
        }
        __syncthreads();
    }

#pragma unroll
    for (int i = 0; i < 8; i++) {
        int row = m0 + trow * 8 + i;
        int colb = n0 + tcol * 4;
        float2 a01 = unpack2(acc01[i]);
        float2 a23 = unpack2(acc23[i]);
        if (MODE == 0) {
            float4 bv = *(const float4*)&bias[colb];
            float4 o;
            o.x = a01.x + bv.x;
            o.y = a01.y + bv.y;
            o.z = a23.x + bv.z;
            o.w = a23.y + bv.w;
            *(float4*)&C[(long)row * N + colb] = o;
        } else {
            float av[4] = {a01.x, a01.y, a23.x, a23.y};
#pragma unroll
            for (int j = 0; j < 4; j++) {
                int col = colb + j;
                int g = col >> 10;
                int cl = col & 1023;
                C[((long)row * 1024 + cl) * 4 + g] = av[j];
            }
        }
    }
}

// ---------------- init: h0 = c0 = mean(Af), scores0 = h0·Af, g_bar = 0 ------
__global__ void __launch_bounds__(256) init_kernel(const float* __restrict__ A) {
    const int n = blockIdx.x;
    const int tid = threadIdx.x;
    __shared__ float sc[256][16];

    if (n == 0 && tid == 0) g_bar = 0u;

    float accl[16];
#pragma unroll
    for (int l = 0; l < 16; l++) accl[l] = 0.0f;

    for (int h = tid; h < HH; h += 256) {
        const float* ar = A + ((n << 10) + h) * 16;
        float a[16];
        float4 v0 = *(const float4*)&ar[0];
        float4 v1 = *(const float4*)&ar[4];
        float4 v2 = *(const float4*)&ar[8];
        float4 v3 = *(const float4*)&ar[12];
        a[0]=v0.x; a[1]=v0.y; a[2]=v0.z; a[3]=v0.w;
        a[4]=v1.x; a[5]=v1.y; a[6]=v1.z; a[7]=v1.w;
        a[8]=v2.x; a[9]=v2.y; a[10]=v2.z; a[11]=v2.w;
        a[12]=v3.x; a[13]=v3.y; a[14]=v3.z; a[15]=v3.w;
        float s = 0.0f;
#pragma unroll
        for (int l = 0; l < 16; l++) s += a[l];
        s *= (1.0f / 16.0f);
        g_hT[0][(h << 6) + n] = make_float2(s, s);   // layout [c][n]
#pragma unroll
        for (int l = 0; l < 16; l++) accl[l] += s * a[l];
    }
#pragma unroll
    for (int l = 0; l < 16; l++) sc[tid][l] = accl[l];
    __syncthreads();
    if (tid < 16) {
        float s = 0.0f;
        for (int j = 0; j < 256; j++) s += sc[j][tid];
        g_scores[0][n * 16 + tid] = s;
        g_scores[1][n * 16 + tid] = 0.0f;
        g_scores[2][n * 16 + tid] = 0.0f;
    }
}

// ---------------- persistent weight-stationary recurrence ----------------
// grid = 128 CTAs x 256 threads, 1 CTA/SM (forced by smem), all co-resident.
// CTA cb owns gate-columns c in [cb*8, cb*8+8) for all 64 n and all 128 steps.
// SMEM: Wh slice 128KB + 3-stage h buffers 48KB + A slice 32KB + softmax 4KB + cell 2KB.
#define SM_WH   0
#define SM_H    131072
#define SM_A    (131072 + 49152)
#define SM_WS   (131072 + 49152 + 32768)
#define SM_C    (131072 + 49152 + 32768 + 4096)
#define SM_TOT  (131072 + 49152 + 32768 + 4096 + 2048)

__global__ void __launch_bounds__(256, 1) persist_kernel(const float* __restrict__ A,
                                                         float* __restrict__ out) {
    extern __shared__ char smem[];
    float4* sWh4 = (float4*)(smem + SM_WH);   // [1024][8]
    float2* sH   = (float2*)(smem + SM_H);    // [3][32][64]
    float*  sA   = (float*)(smem + SM_A);     // [16 l][64 n][8 c]
    float*  ws   = (float*)(smem + SM_WS);    // [16 l][64 n]
    float*  sC   = (float*)(smem + SM_C);     // [64 n][8 c]

    const int tid = threadIdx.x;
    const int cb  = blockIdx.x;               // 0..127
    const int np  = tid >> 3;                 // 0..31
    const int cq  = tid & 7;                  // 0..7
    const int n0  = np * 2, n1 = n0 + 1;
    const int cglob = cb * 8 + cq;

    // ---- one-time loads: Wh slice (cp.async), A slice (transposed), cell ----
#pragma unroll
    for (int j = 0; j < 32; j++) {
        int i = tid + j * 256;                // 0..8191
        int kl = i >> 3, cj = i & 7;
        cp_async16(smem_u32(&sWh4[kl * 8 + cj]),
                   &((const float4*)g_WhT)[kl * 1024 + cb * 8 + cj]);
    }
    asm volatile("cp.async.commit_group;" ::: "memory");
#pragma unroll
    for (int j = 0; j < 32; j++) {
        int i = tid + j * 256;                // 0..8191
        int l = i & 15, c = (i >> 4) & 7, n = i >> 7;
        sA[l * 512 + n * 8 + c] = A[((n << 10) + cb * 8 + c) * 16 + l];
    }
#pragma unroll
    for (int j = 0; j < 2; j++) {
        int i = tid + j * 256;                // 0..511
        int n = i >> 3, c = i & 7;
        sC[i] = g_hT[0][((cb * 8 + c) << 6) + n].x;
    }
    asm volatile("cp.async.wait_group 0;" ::: "memory");
    __syncthreads();

#define STAGE(kb_, b_) do {                                                    \
        int k0_ = (kb_) << 5;                                                  \
        _Pragma("unroll")                                                      \
        for (int j_ = 0; j_ < 4; j_++) {                                       \
            int i_ = tid + j_ * 256;                                           \
            int kl_ = i_ >> 5, nq_ = i_ & 31;                                  \
            cp_async16(smem_u32(&sH[((b_) * 32 + kl_) * 64 + nq_ * 2]),        \
                       &hsrc[((k0_ + kl_) << 6) + nq_ * 2]);                   \
        }                                                                      \
        asm volatile("cp.async.commit_group;" ::: "memory");                   \
    } while (0)

    for (int t = 0; t < TT; t++) {
        const int prev = t & 1, cur = prev ^ 1;
        const float2* hsrc = g_hT[prev];
        const float* sc_in = g_scores[t % 3];
        float* sc_out  = g_scores[(t + 1) % 3];
        float* sc_zero = g_scores[(t + 2) % 3];

        // prefetch first two h chunks (h_prev valid: written before last barrier)
        STAGE(0, 0);
        STAGE(1, 1);

        // redundant per-CTA softmax over all 64 rows
        if (tid < 64) {
            int n = tid;
            float s[16];
            float m = -1e30f;
#pragma unroll
            for (int l = 0; l < 16; l++) {
                s[l] = __ldcg(&sc_in[n * 16 + l]) * 0.03125f;  // 1/sqrt(1024)
                m = fmaxf(m, s[l]);
            }
            float sum = 0.0f;
#pragma unroll
            for (int l = 0; l < 16; l++) { s[l] = expf(s[l] - m); sum += s[l]; }
            float inv = 1.0f / sum;
#pragma unroll
            for (int l = 0; l < 16; l++) ws[l * 64 + n] = s[l] * inv;
        }
        if (tid < 8) sc_zero[cb * 8 + tid] = 0.0f;   // 128 CTAs x 8 = 1024
        __syncthreads();

        // acc init from Xa (original layout; 8 scalar LDG per n, sector-shared)
        unsigned long long a01_0, a23_0, a01_1, a23_1;
        {
            const float* xa0 = g_Xa + (long)(n0 * TT + t) * G4 + cglob;
            const float* xa1 = g_Xa + (long)(n1 * TT + t) * G4 + cglob;
            a01_0 = pack2(xa0[0], xa0[1024]);
            a23_0 = pack2(xa0[2048], xa0[3072]);
            a01_1 = pack2(xa1[0], xa1[1024]);
            a23_1 = pack2(xa1[2048], xa1[3072]);
        }

        // attention term: a += w @ P (overlaps with h-chunk prefetch)
        const ulonglong2* Pu = (const ulonglong2*)g_P;
#pragma unroll
        for (int l = 0; l < 16; l++) {
            unsigned long long w0 = dup2(ws[l * 64 + n0]);
            unsigned long long w1 = dup2(ws[l * 64 + n1]);
            ulonglong2 p0 = Pu[(n0 * 16 + l) * 1024 + cglob];
            ulonglong2 p1 = Pu[(n1 * 16 + l) * 1024 + cglob];
            a01_0 = fma2(w0, p0.x, a01_0);
            a23_0 = fma2(w0, p0.y, a23_0);
            a01_1 = fma2(w1, p1.x, a01_1);
            a23_1 = fma2(w1, p1.y, a23_1);
        }

        // main recurrent GEMM: 32 chunks of 32 k, 3-stage cp.async pipeline
        for (int kb = 0; kb < 32; kb++) {
            if (kb < 31) asm volatile("cp.async.wait_group 1;" ::: "memory");
            else         asm volatile("cp.async.wait_group 0;" ::: "memory");
            __syncthreads();
            if (kb < 30) STAGE(kb + 2, (kb + 2) % 3);

            const int b = kb % 3;
#pragma unroll 8
            for (int kk = 0; kk < 32; kk++) {
                ulonglong2 hv = *(const ulonglong2*)&sH[(b * 32 + kk) * 64 + n0];
                ulonglong2 w  = *(const ulonglong2*)&sWh4[(kb * 32 + kk) * 8 + cq];
                a01_0 = fma2(hv.x, w.x, a01_0);
                a23_0 = fma2(hv.x, w.y, a23_0);
                a01_1 = fma2(hv.y, w.x, a01_1);
                a23_1 = fma2(hv.y, w.y, a23_1);
            }
        }

        // LSTM epilogue (cell state lives in SMEM, owned exclusively)
        float2 A01_0 = unpack2(a01_0), A23_0 = unpack2(a23_0);
        float2 A01_1 = unpack2(a01_1), A23_1 = unpack2(a23_1);

        float i0 = 1.0f / (1.0f + expf(-A01_0.x));
        float f0 = 1.0f / (1.0f + expf(-A01_0.y));
        float o0 = 1.0f / (1.0f + expf(-A23_0.x));
        float g0 = tanhf(A23_0.y);
        float cp0 = sC[n0 * 8 + cq];
        float cn0 = f0 * cp0 + i0 * g0;
        float h0 = o0 * tanhf(cn0);
        sC[n0 * 8 + cq] = cn0;

        float i1 = 1.0f / (1.0f + expf(-A01_1.x));
        float f1 = 1.0f / (1.0f + expf(-A01_1.y));
        float o1 = 1.0f / (1.0f + expf(-A23_1.x));
        float g1 = tanhf(A23_1.y);
        float cp1 = sC[n1 * 8 + cq];
        float cn1 = f1 * cp1 + i1 * g1;
        float h1 = o1 * tanhf(cn1);
        sC[n1 * 8 + cq] = cn1;

        // publish h (quad-dup layout) + output
        float4 hq = make_float4(h0, h0, h1, h1);
        *(float4*)&g_hT[cur][(cglob << 6) + n0] = hq;
        out[(long)(n0 * TT + t) * HH + cglob] = h0;
        out[(long)(n1 * TT + t) * HH + cglob] = h1;

        // next-step score partials: reduce over this CTA's 8 c via shfl, atomicAdd
#pragma unroll
        for (int l = 0; l < 16; l++) {
            float v0 = h0 * sA[l * 512 + n0 * 8 + cq];
            float v1 = h1 * sA[l * 512 + n1 * 8 + cq];
            v0 += __shfl_xor_sync(0xffffffffu, v0, 1);
            v1 += __shfl_xor_sync(0xffffffffu, v1, 1);
            v0 += __shfl_xor_sync(0xffffffffu, v0, 2);
            v1 += __shfl_xor_sync(0xffffffffu, v1, 2);
            v0 += __shfl_xor_sync(0xffffffffu, v0, 4);
            v1 += __shfl_xor_sync(0xffffffffu, v1, 4);
            if (cq == 0) {
                atomicAdd(&sc_out[n0 * 16 + l], v0);
                atomicAdd(&sc_out[n1 * 16 + l], v1);
            }
        }

        // ---- global barrier ----
        __threadfence();
        __syncthreads();
        if (tid == 0) {
            atomicAdd((unsigned*)&g_bar, 1u);
            unsigned tgt = 128u * (unsigned)(t + 1);
            while (g_bar < tgt) { }
            __threadfence();
        }
        __syncthreads();
    }
#undef STAGE
}

// ---------------- launcher ----------------
extern "C" void kernel_launch(void* const* d_in, const int* in_sizes, int n_in,
                              void* d_out, int out_size) {
    const float* x     = (const float*)d_in[0];
    const float* A     = (const float*)d_in[1];
    const float* Wx    = (const float*)d_in[2];
    const float* Wh    = (const float*)d_in[3];
    const float* Wattn = (const float*)d_in[4];
    const float* b     = (const float*)d_in[5];
    float* out = (float*)d_out;

    cudaFuncSetAttribute(persist_kernel, cudaFuncAttributeMaxDynamicSharedMemorySize,
                         SM_TOT);

    pack_wh_kernel<<<4096, 256>>>(Wh);
    transposeA_kernel<<<4096, 256>>>(A);
    // Xa = x @ Wx + b : M=8192, N=4096, K=512
    sgemm_kernel<0><<<dim3(G4 / 64, (NN * TT) / 128), 256>>>(x, Wx, b, NN * TT, G4, DD);
    // P = A2 @ Wattn  : M=1024, N=4096, K=1024 (packed output)
    sgemm_kernel<1><<<dim3(G4 / 64, (NN * 16) / 128), 256>>>(nullptr, Wattn, nullptr,
                                                             NN * 16, G4, HH);
    init_kernel<<<NN, 256>>>(A);

    // all 128 timesteps inside one persistent kernel
    persist_kernel<<<128, 256, SM_TOT>>>(A, out);
}